// round 13
// baseline (speedup 1.0000x reference)
#include <cuda_runtime.h>
#include <cuda_bf16.h>
#include <cuda_fp16.h>
#include <cstdint>
#include <cstddef>

// ---------------- problem constants ----------------
#define BATCH   8
#define P       2784
#define PM1     2783
#define FH      11
#define FW      20
#define HW      220
#define CIN     512
#define AFC     64
#define DIM     704
#define DIM2    1408
#define NWOUT   75
#define M_TOT   (BATCH*P)   // 22272 = 174*128
#define AKH     40          // bf16 k-major smem pitch in halfs (32 data + 8 pad)
#define BNH     136         // gemm3 B (n-major) smem pitch in halfs (128 + 8 pad)
#define AP8     80          // fp8 smem pitch in bytes (64 data + 16 pad)
#define RP      128         // R row pitch (bf16), cols 75..127 zero
#define FP      80          // F row pitch (fp32)
#define FEAT_SCALE 64.0f
#define ATTW_SCALE 256.0f
#define SCORE_INV  (1.0f/16384.0f)
#define LOG2E      1.4426950408889634f

// ---------------- scratch ----------------
__device__ float          g_f[BATCH*AFC*HW];
__device__ float          g_feat[(size_t)M_TOT*DIM];          // fp32 feat (k_head)
__device__ unsigned char  g_feat8[(size_t)M_TOT*DIM];         // e4m3 feat*64 (gemm1)
__device__ unsigned char  g_attw8[(size_t)PM1*DIM];           // e4m3 att_w*256 (gemm1)
__device__ __nv_bfloat16  g_attb16[(size_t)M_TOT*PM1];        // bf16 scores
__device__ __nv_bfloat16  g_attsh[(size_t)M_TOT*P];           // bf16 SHIFTED softmax (dense PxP)
__device__ __nv_bfloat16  g_Rb[(size_t)M_TOT*RP];             // bf16 R = feat @ Wa^T (padded)
__device__ float          g_F[(size_t)M_TOT*FP];              // fp32 F = feat @ Wf^T
__device__ unsigned char  g_inv[P*FH];

// ---------------- helpers ----------------
__device__ __forceinline__ void mma_bf16(float* c, const uint32_t* a, const uint32_t* b) {
    asm volatile("mma.sync.aligned.m16n8k16.row.col.f32.bf16.bf16.f32 "
                 "{%0,%1,%2,%3}, {%4,%5,%6,%7}, {%8,%9}, {%0,%1,%2,%3};"
                 : "+f"(c[0]), "+f"(c[1]), "+f"(c[2]), "+f"(c[3])
                 : "r"(a[0]), "r"(a[1]), "r"(a[2]), "r"(a[3]),
                   "r"(b[0]), "r"(b[1]));
}
__device__ __forceinline__ void mma_f8(float* c, const uint32_t* a, uint32_t b0, uint32_t b1) {
    asm volatile("mma.sync.aligned.m16n8k32.row.col.f32.e4m3.e4m3.f32 "
                 "{%0,%1,%2,%3}, {%4,%5,%6,%7}, {%8,%9}, {%0,%1,%2,%3};"
                 : "+f"(c[0]), "+f"(c[1]), "+f"(c[2]), "+f"(c[3])
                 : "r"(a[0]), "r"(a[1]), "r"(a[2]), "r"(a[3]),
                   "r"(b0), "r"(b1));
}
__device__ __forceinline__ void cpa16(uint32_t s, const void* g) {
    asm volatile("cp.async.cg.shared.global [%0], [%1], 16;" :: "r"(s), "l"(g));
}
__device__ __forceinline__ void cpa16p(uint32_t s, const void* g, int pred) {
    int sz = pred ? 16 : 0;
    asm volatile("cp.async.cg.shared.global [%0], [%1], 16, %2;" :: "r"(s), "l"(g), "r"(sz));
}
__device__ __forceinline__ uint32_t svta(const void* p) {
    return (uint32_t)__cvta_generic_to_shared(p);
}
__device__ __forceinline__ void ldsm4(uint32_t* r, uint32_t a) {
    asm volatile("ldmatrix.sync.aligned.m8n8.x4.shared.b16 {%0,%1,%2,%3}, [%4];"
                 : "=r"(r[0]), "=r"(r[1]), "=r"(r[2]), "=r"(r[3]) : "r"(a));
}
__device__ __forceinline__ void ldsm4t(uint32_t* r, uint32_t a) {
    asm volatile("ldmatrix.sync.aligned.m8n8.x4.trans.shared.b16 {%0,%1,%2,%3}, [%4];"
                 : "=r"(r[0]), "=r"(r[1]), "=r"(r[2]), "=r"(r[3]) : "r"(a));
}
__device__ __forceinline__ unsigned char f2e4m3(float x) {
    uint16_t r;
    asm("cvt.rn.satfinite.e4m3x2.f32 %0, %1, %2;" : "=h"(r) : "f"(0.0f), "f"(x));
    return (unsigned char)(r & 0xFF);
}

// ---------------- invalid-dtype detection + normalization --------------------
__global__ void k_detect_inv(const unsigned char* __restrict__ raw) {
    __shared__ int f_gt1, f_mod;
    if (threadIdx.x == 0) { f_gt1 = 0; f_mod = 0; }
    __syncthreads();
    const int NB = P * FH;
    int lg = 0, lm = 0;
    for (int i = threadIdx.x; i < NB; i += blockDim.x) {
        unsigned char v = raw[i];
        if (v > 1) lg = 1;
        if (v != 0 && (i & 3) != 0) lm = 1;
    }
    if (lg) atomicOr(&f_gt1, 1);
    if (lm) atomicOr(&f_mod, 1);
    __syncthreads();
    int mode = f_gt1 ? 2 : (f_mod ? 0 : 1);
    for (int i = threadIdx.x; i < NB; i += blockDim.x) {
        unsigned char o;
        if (mode == 0)      o = (raw[i] != 0);
        else if (mode == 1) o = (((const int*)raw)[i] != 0);
        else                o = (((const float*)raw)[i] != 0.0f);
        g_inv[i] = o;
    }
}

// ---------------- 1x1 conv ----------------
__global__ void k_conv(const float* __restrict__ x,
                       const float* __restrict__ w,
                       const float* __restrict__ bias) {
    __shared__ float xs[CIN];
    const int b = blockIdx.y, s = blockIdx.x;
    const int t = threadIdx.x;
    for (int c = t; c < CIN; c += 64)
        xs[c] = x[(size_t)(b*CIN + c)*HW + s];
    __syncthreads();
    float acc = bias[t];
    const float4* wp = (const float4*)(w + (size_t)t*CIN);
#pragma unroll 8
    for (int c4 = 0; c4 < CIN/4; c4++) {
        float4 wv = wp[c4];
        acc += xs[4*c4+0]*wv.x + xs[4*c4+1]*wv.y + xs[4*c4+2]*wv.z + xs[4*c4+3]*wv.w;
    }
    g_f[(size_t)(b*AFC + t)*HW + s] = acc;
}

// ---------------- att_w -> e4m3 (scaled x256) ----------------
__global__ void k_cvt_attw(const float* __restrict__ w) {
    int i = blockIdx.x*256 + threadIdx.x;
    if (i < PM1*DIM) g_attw8[i] = f2e4m3(w[i] * ATTW_SCALE);
}

// ---------------- gather (fp32 + e4m3 outputs) ----------------
__global__ void k_gather(const int* __restrict__ cut_x) {
    const int row = blockIdx.x;
    const int b = row / P, p = row - b*P;
    __shared__ int cx[FH];
    __shared__ unsigned char iv[FH];
    if (threadIdx.x < FH) {
        cx[threadIdx.x] = cut_x[p*FH + threadIdx.x];
        iv[threadIdx.x] = g_inv[p*FH + threadIdx.x];
    }
    __syncthreads();
    for (int d = threadIdx.x; d < DIM; d += blockDim.x) {
        int c = d / FH, h = d - c*FH;
        float v = iv[h] ? 0.0f : g_f[(size_t)(b*AFC + c)*HW + h*FW + cx[h]];
        g_feat[(size_t)row*DIM + d]  = v;
        g_feat8[(size_t)row*DIM + d] = f2e4m3(v * FEAT_SCALE);
    }
}

// ============== k_head: R = feat @ Wa^T (bf16 out), F = feat @ Wf^T (fp32) ===
#define SPAD 132
#define NH 160
__global__ __launch_bounds__(256) void k_head(const float* __restrict__ cls_w,
                                              const float* __restrict__ reg_w) {
    __shared__ float As2[16][SPAD];
    __shared__ float Ws[16][NH];
    const int m0 = blockIdx.x * 128;
    const int tid = threadIdx.x;
    const int ty = tid >> 4, tx = tid & 15;
    float acc[8][10];
#pragma unroll
    for (int i = 0; i < 8; i++)
#pragma unroll
        for (int j = 0; j < 10; j++) acc[i][j] = 0.0f;

    for (int k0 = 0; k0 < DIM; k0 += 16) {
#pragma unroll
        for (int q = 0; q < 2; q++) {
            int idx = tid + q*256;
            int r = idx >> 2, c4 = (idx & 3) << 2;
            float4 v = *(const float4*)(g_feat + (size_t)(m0 + r)*DIM + k0 + c4);
            As2[c4+0][r] = v.x; As2[c4+1][r] = v.y; As2[c4+2][r] = v.z; As2[c4+3][r] = v.w;
        }
        for (int i = tid; i < 16*NH; i += 256) {
            int kk = i / NH, n = i - kk*NH;
            int half = (n >= 80) ? 1 : 0;
            int nn = n - 80*half;
            int col = k0 + kk + 704*half;
            float v = 0.0f;
            if (nn < 2)          v = cls_w[(size_t)nn*DIM2 + col];
            else if (nn < NWOUT) v = reg_w[(size_t)(nn-2)*DIM2 + col];
            Ws[kk][n] = v;
        }
        __syncthreads();
#pragma unroll
        for (int kk = 0; kk < 16; kk++) {
            float a[8], w[10];
            *(float4*)(a)   = *(const float4*)&As2[kk][ty*8];
            *(float4*)(a+4) = *(const float4*)&As2[kk][ty*8+4];
#pragma unroll
            for (int j = 0; j < 10; j++) w[j] = Ws[kk][tx*10 + j];
#pragma unroll
            for (int i = 0; i < 8; i++)
#pragma unroll
                for (int j = 0; j < 10; j++) acc[i][j] += a[i]*w[j];
        }
        __syncthreads();
    }
#pragma unroll
    for (int i = 0; i < 8; i++) {
        int row = m0 + ty*8 + i;
#pragma unroll
        for (int j = 0; j < 10; j++) {
            int n = tx*10 + j;
            if (n < NWOUT)
                g_Rb[(size_t)row*RP + n] = __float2bfloat16(acc[i][j]);
            else if (n < 80)
                g_Rb[(size_t)row*RP + n] = __float2bfloat16(0.0f);
            else {
                int nn = n - 80;
                if (nn < NWOUT) g_F[(size_t)row*FP + nn] = acc[i][j];
            }
        }
        for (int c = 80 + tx; c < RP; c += 16)
            g_Rb[(size_t)row*RP + c] = __float2bfloat16(0.0f);
    }
}

// ============== GEMM1 (e4m3 mma k32 + ldmatrix, cp.async double-buffered) ====
__global__ __launch_bounds__(256) void k_gemm1_f8(const float* __restrict__ bias) {
    __shared__ __align__(16) unsigned char As[2][128*AP8];
    __shared__ __align__(16) unsigned char Bs[2][128*AP8];
    const int bm = blockIdx.y*128, bn = blockIdx.x*128;
    const int tid = threadIdx.x, lane = tid & 31, wid = tid >> 5;
    const int wm = (wid >> 2)*64, wn = (wid & 3)*32;
    const int g = lane >> 2, t4 = lane & 3;
    float acc[4][4][4];
#pragma unroll
    for (int i = 0; i < 4; i++)
#pragma unroll
        for (int j = 0; j < 4; j++)
#pragma unroll
            for (int r = 0; r < 4; r++) acc[i][j][r] = 0.0f;

    const int a_off = (wm + (lane & 7) + 8*((lane >> 3) & 1))*AP8 + 16*(lane >> 4);
    const int b_off = (wn + (lane & 7) + 8*((lane >> 3) & 1))*AP8 + 16*(lane >> 4);
    const uint32_t AsB[2] = { svta(&As[0][0]), svta(&As[1][0]) };
    const uint32_t BsB[2] = { svta(&Bs[0][0]), svta(&Bs[1][0]) };

    auto stage = [&](int buf, int k0) {
#pragma unroll
        for (int q = 0; q < 2; q++) {
            int idx = tid + q*256;
            int r = idx >> 2, c16 = (idx & 3) << 4;
            cpa16(svta(&As[buf][r*AP8 + c16]),
                  g_feat8 + (size_t)(bm + r)*DIM + k0 + c16);
            int n = bn + r;
            int ok = (n < PM1);
            cpa16p(svta(&Bs[buf][r*AP8 + c16]),
                   g_attw8 + (size_t)(ok ? n : 0)*DIM + k0 + c16, ok);
        }
    };

    stage(0, 0);
    asm volatile("cp.async.commit_group;");
    int buf = 0;
    const int NK = DIM/64;   // 11
    for (int it = 0; it < NK; it++) {
        if (it + 1 < NK) {
            stage(buf ^ 1, (it + 1)*64);
            asm volatile("cp.async.commit_group;");
            asm volatile("cp.async.wait_group 1;");
        } else {
            asm volatile("cp.async.wait_group 0;");
        }
        __syncthreads();
#pragma unroll
        for (int ks = 0; ks < 2; ks++) {
            uint32_t af[4][4], bq[2][4];
#pragma unroll
            for (int mt = 0; mt < 4; mt++)
                ldsm4(af[mt], AsB[buf] + a_off + mt*16*AP8 + ks*32);
#pragma unroll
            for (int ntp = 0; ntp < 2; ntp++)
                ldsm4(bq[ntp], BsB[buf] + b_off + ntp*16*AP8 + ks*32);
#pragma unroll
            for (int mt = 0; mt < 4; mt++)
#pragma unroll
                for (int nt = 0; nt < 4; nt++) {
                    int ntp = nt >> 1, sub = nt & 1;
                    mma_f8(acc[mt][nt], af[mt], bq[ntp][sub], bq[ntp][sub + 2]);
                }
        }
        __syncthreads();
        buf ^= 1;
    }
#pragma unroll
    for (int mt = 0; mt < 4; mt++) {
        int r0 = bm + wm + mt*16 + g;
#pragma unroll
        for (int nt = 0; nt < 4; nt++) {
            int n0 = bn + wn + nt*8 + t4*2;
            if (n0 < PM1)
                g_attb16[(size_t)r0*PM1 + n0]       = __float2bfloat16(acc[mt][nt][0]*SCORE_INV + bias[n0]);
            if (n0+1 < PM1)
                g_attb16[(size_t)r0*PM1 + n0+1]     = __float2bfloat16(acc[mt][nt][1]*SCORE_INV + bias[n0+1]);
            if (n0 < PM1)
                g_attb16[(size_t)(r0+8)*PM1 + n0]   = __float2bfloat16(acc[mt][nt][2]*SCORE_INV + bias[n0]);
            if (n0+1 < PM1)
                g_attb16[(size_t)(r0+8)*PM1 + n0+1] = __float2bfloat16(acc[mt][nt][3]*SCORE_INV + bias[n0+1]);
        }
    }
}

// ---------------- softmax: bf16 in, f16x2 exp, bf16 SHIFTED dense row out ----
// MUFU halved: one ex2.approx.f16x2 computes two exps. Normalizer in fp32.
#define SITER ((PM1 + 255)/256)   // 11
__global__ __launch_bounds__(256) void k_softmax() {
    __shared__ float red[256];
    const size_t base  = (size_t)blockIdx.x * PM1;
    const size_t obase = (size_t)blockIdx.x * P;
    const int m = blockIdx.x % P;
    const int t = threadIdx.x;
    float vals[SITER];
    float mx = -1e30f;
#pragma unroll
    for (int j = 0; j < SITER; j++) {
        int i = t + j*256;
        float v = (i < PM1) ? __bfloat162float(g_attb16[base + i]) : -1e30f;
        vals[j] = v; mx = fmaxf(mx, v);
    }
    red[t] = mx; __syncthreads();
    for (int s = 128; s > 0; s >>= 1) { if (t < s) red[t] = fmaxf(red[t], red[t+s]); __syncthreads(); }
    mx = red[0]; __syncthreads();
    float sum = 0.0f;
    const float nm = -mx * LOG2E;
#pragma unroll
    for (int j = 0; j + 1 < SITER; j += 2) {
        // two exps per MUFU via ex2.approx.f16x2; OOB lanes hold -1e30 -> -inf -> 0
        __half2 h = __floats2half2_rn(fmaf(vals[j],   LOG2E, nm),
                                      fmaf(vals[j+1], LOG2E, nm));
        __half2 e = h2exp2(h);
        float2 f = __half22float2(e);
        vals[j] = f.x; vals[j+1] = f.y;
        sum += f.x + f.y;
    }
    {   // odd tail element (j = SITER-1)
        int i = t + (SITER-1)*256;
        float e = (i < PM1) ? __expf(vals[SITER-1] - mx) : 0.0f;
        vals[SITER-1] = e; sum += e;
    }
    red[t] = sum; __syncthreads();
    for (int s = 128; s > 0; s >>= 1) { if (t < s) red[t] += red[t+s]; __syncthreads(); }
    float inv = 1.0f / red[0];
#pragma unroll
    for (int j = 0; j < SITER; j++) {
        int i = t + j*256;
        if (i < PM1)
            g_attsh[obase + i + (i >= m)] = __float2bfloat16(vals[j] * inv);
    }
    if (t == 0) g_attsh[obase + m] = __float2bfloat16(0.0f);
}

// ============== GEMM3 (bf16 mma): out = A_shift @ R + F + bias + anchors =====
__global__ __launch_bounds__(256) void k_gemm3_bf(const float* __restrict__ cls_b,
                                                  const float* __restrict__ reg_b,
                                                  const float* __restrict__ anchors,
                                                  float* __restrict__ out) {
    __shared__ __align__(16) __nv_bfloat16 As[2][128*AKH];
    __shared__ __align__(16) __nv_bfloat16 Bs[2][32*BNH];
    const int b  = blockIdx.z;
    const int m0 = blockIdx.y*128;
    const int tid = threadIdx.x, lane = tid & 31, wid = tid >> 5;
    const int wm = (wid >> 2)*64, wn = (wid & 3)*32;
    const int g = lane >> 2, t4 = lane & 3;
    const __nv_bfloat16* attsh = g_attsh + (size_t)b*P*P;
    const __nv_bfloat16* Rb    = g_Rb    + (size_t)b*P*RP;
    float acc[4][4][4];
#pragma unroll
    for (int i = 0; i < 4; i++)
#pragma unroll
        for (int j = 0; j < 4; j++)
#pragma unroll
            for (int r = 0; r < 4; r++) acc[i][j][r] = 0.0f;

    const int a_off  = (wm + (lane & 7) + 8*((lane >> 3) & 1))*AKH + 8*(lane >> 4);
    const int bt_off = ((lane & 7) + 8*((lane >> 3) & 1))*BNH + wn + 8*(lane >> 4);
    const uint32_t AsB[2] = { svta(&As[0][0]), svta(&As[1][0]) };
    const uint32_t BsB[2] = { svta(&Bs[0][0]), svta(&Bs[1][0]) };

    auto stage = [&](int buf, int k0) {
#pragma unroll
        for (int q = 0; q < 2; q++) {
            int idx = tid + q*256;
            int r = idx >> 2, c8 = (idx & 3) << 3;
            int gm = m0 + r;
            int ok = (gm < P);
            cpa16p(svta(&As[buf][r*AKH + c8]),
                   attsh + (size_t)(ok ? gm : 0)*P + k0 + c8, ok);
        }
#pragma unroll
        for (int q = 0; q < 2; q++) {
            int idx = tid + q*256;
            int kr = idx >> 4, c8 = (idx & 15) << 3;
            cpa16(svta(&Bs[buf][kr*BNH + c8]),
                  Rb + (size_t)(k0 + kr)*RP + c8);
        }
    };

    stage(0, 0);
    asm volatile("cp.async.commit_group;");
    int buf = 0;
    const int NK = P/32;   // 87
    for (int it = 0; it < NK; it++) {
        if (it + 1 < NK) {
            stage(buf ^ 1, (it + 1)*32);
            asm volatile("cp.async.commit_group;");
            asm volatile("cp.async.wait_group 1;");
        } else {
            asm volatile("cp.async.wait_group 0;");
        }
        __syncthreads();
#pragma unroll
        for (int ks = 0; ks < 2; ks++) {
            const int kk = ks*16;
            uint32_t af[4][4], bq[2][4];
#pragma unroll
            for (int mt = 0; mt < 4; mt++)
                ldsm4(af[mt], AsB[buf] + 2*(a_off + mt*16*AKH + kk));
#pragma unroll
            for (int ntp = 0; ntp < 2; ntp++)
                ldsm4t(bq[ntp], BsB[buf] + 2*(bt_off + kk*BNH + ntp*16));
#pragma unroll
            for (int mt = 0; mt < 4; mt++)
#pragma unroll
                for (int nt = 0; nt < 4; nt++)
                    mma_bf16(acc[mt][nt], af[mt], &bq[nt >> 1][(nt & 1)*2]);
        }
        __syncthreads();
        buf ^= 1;
    }

    // fused final epilogue: add F + bias, then anchors/output assembly
    const size_t O0 = 0;
    const size_t O1 = (size_t)M_TOT * 72;
    const size_t O2 = O1 + M_TOT;
    const size_t O3 = O2 + M_TOT;
#pragma unroll
    for (int mt = 0; mt < 4; mt++) {
        int r0 = m0 + wm + mt*16 + g;
#pragma unroll
        for (int nt = 0; nt < 4; nt++) {
            int n0c = wn + nt*8 + t4*2;
#pragma unroll
            for (int rr = 0; rr < 2; rr++) {
                int pl = r0 + 8*rr;
                if (pl >= P) continue;
                int row = b*P + pl;
#pragma unroll
                for (int e = 0; e < 2; e++) {
                    int n = n0c + e;
                    if (n >= NWOUT) continue;
                    float val = acc[mt][nt][rr*2 + e]
                              + g_F[(size_t)row*FP + n]
                              + (n < 2 ? cls_b[n] : reg_b[n-2]);
                    if (n < 2) {
                        out[O3 + (size_t)row*2 + n] = val;
                    } else if (n == 2) {
                        out[O2 + row] = anchors[pl*74 + 1] + val;
                        out[O1 + row] = anchors[pl*74 + 0];
                    } else {
                        out[O0 + (size_t)row*72 + (n-3)] = anchors[pl*74 + 2 + (n-3)] + val;
                    }
                }
            }
        }
    }
}

// ---------------- launch ----------------
extern "C" void kernel_launch(void* const* d_in, const int* in_sizes, int n_in,
                              void* d_out, int out_size) {
    const float* x       = (const float*)d_in[0];
    const float* conv_w  = (const float*)d_in[1];
    const float* conv_b  = (const float*)d_in[2];
    const float* att_w   = (const float*)d_in[3];
    const float* att_b   = (const float*)d_in[4];
    const float* cls_w   = (const float*)d_in[5];
    const float* cls_b   = (const float*)d_in[6];
    const float* reg_w   = (const float*)d_in[7];
    const float* reg_b   = (const float*)d_in[8];
    const float* anchors = (const float*)d_in[9];
    const int*   cut_x   = (const int*)d_in[10];
    const unsigned char* invalid = (const unsigned char*)d_in[11];
    float* out = (float*)d_out;
    (void)in_sizes; (void)n_in; (void)out_size;

    k_detect_inv<<<1, 1024>>>(invalid);
    k_conv<<<dim3(HW, BATCH), 64>>>(x, conv_w, conv_b);
    k_cvt_attw<<<(PM1*DIM + 255)/256, 256>>>(att_w);
    k_gather<<<M_TOT, 128>>>(cut_x);
    k_head<<<M_TOT/128, 256>>>(cls_w, reg_w);
    k_gemm1_f8<<<dim3((PM1 + 127)/128, M_TOT/128), 256>>>(att_b);
    k_softmax<<<M_TOT, 256>>>();
    k_gemm3_bf<<<dim3(1, (P + 127)/128, BATCH), 256>>>(cls_b, reg_b, anchors, out);
}